// round 12
// baseline (speedup 1.0000x reference)
#include <cuda_runtime.h>
#include <cuda_bf16.h>
#include <cstdint>

// Problem shape (fixed by the dataset)
static constexpr int B  = 4;
static constexpr int S  = 4096;
static constexpr int D  = 4096;
static constexpr int D4 = D / 4;             // 1024 float4 per (b, s) row

// Tiling: each block owns CH float4-channels for the FULL sequence.
static constexpr int CH    = 16;             // float4 channel-groups per block (64 scalar channels)
static constexpr int SEG   = 16;             // s-segments per chunk
static constexpr int STEPS = 4;              // s-steps per thread per chunk
static constexpr int L     = SEG * STEPS;    // 64 s-steps per chunk
static constexpr int C     = S / L;          // 64 chunks, processed serially per block
static constexpr int TD    = CH * SEG;       // 256 threads
static constexpr int NB    = (B * D4) / CH;  // 256 blocks (single wave @ 2 CTAs/SM)

__device__ __forceinline__ float4 f4_fma(float4 a, float4 b, float4 c) {
    return make_float4(fmaf(a.x, b.x, c.x), fmaf(a.y, b.y, c.y),
                       fmaf(a.z, b.z, c.z), fmaf(a.w, b.w, c.w));
}
__device__ __forceinline__ float4 f4_mul(float4 a, float4 b) {
    return make_float4(a.x * b.x, a.y * b.y, a.z * b.z, a.w * b.w);
}

struct Smem {
    float4 shA[2][SEG][CH];   // parity-buffered segment aggregates (gate products)
    float4 shB[2][SEG][CH];   // parity-buffered segment aggregates (scan tails)
    float4 shC[2][CH];        // parity-buffered inter-chunk carry broadcast
};

__device__ __forceinline__ void load_chunk(const float4* __restrict__ gates,
                                           const float4* __restrict__ inputs,
                                           size_t base,
                                           float4 (&a)[STEPS], float4 (&v)[STEPS])
{
#pragma unroll
    for (int i = 0; i < STEPS; i++) a[i] = __ldcs(&gates[base + (size_t)i * D4]);
#pragma unroll
    for (int i = 0; i < STEPS; i++) v[i] = __ldcs(&inputs[base + (size_t)i * D4]);
}

// Process one resident chunk. P = compile-time parity. ONE barrier per chunk.
// Stores use default write-back policy: L2 accumulates dirty lines and evicts
// them in long bursts -> fewer DRAM read/write turnarounds than __stcs.
template <int P>
__device__ __forceinline__ void process_chunk(float4 (&a)[STEPS], float4 (&v)[STEPS],
                                              size_t base,
                                              float4* __restrict__ out,
                                              Smem& sm, int seg, int gi)
{
    // Local scan within segment: a -> cumulative gate product, v -> zero-init scan.
#pragma unroll
    for (int i = 1; i < STEPS; i++) {
        v[i] = f4_fma(a[i], v[i - 1], v[i]);
        a[i] = f4_mul(a[i], a[i - 1]);
    }

    // Publish segment aggregate into this chunk's parity buffer.
    sm.shA[P][seg][gi] = a[STEPS - 1];
    sm.shB[P][seg][gi] = v[STEPS - 1];
    __syncthreads();   // orders: this write -> all reads below; prev-chunk carry write -> read

    // Carry entering this chunk (broadcast by last chunk's last-segment threads, or seeded pv).
    const float4 cv = sm.shC[P ^ 1][gi];

    // Exclusive prefix over earlier segments only (avg SEG/2 iterations).
    float4 PA = make_float4(1.f, 1.f, 1.f, 1.f);
    float4 PB = make_float4(0.f, 0.f, 0.f, 0.f);
    for (int j = 0; j < seg; j++) {
        const float4 Aj = sm.shA[P][j][gi];
        const float4 Bj = sm.shB[P][j][gi];
        PB = f4_fma(Aj, PB, Bj);
        PA = f4_mul(Aj, PA);
    }

    // State at segment start.
    const float4 ss = f4_fma(PA, cv, PB);

    // Last segment broadcasts next chunk's carry (read after NEXT chunk's barrier).
    if (seg == SEG - 1) {
        sm.shC[P][gi] = f4_fma(a[STEPS - 1], ss, v[STEPS - 1]);
    }

    // Fix up and store (default write-back: L2-batched writes).
#pragma unroll
    for (int i = 0; i < STEPS; i++) {
        out[base + (size_t)i * D4] = f4_fma(a[i], ss, v[i]);
    }
}

__global__ void __launch_bounds__(TD, 2)
assoc_scan_kernel(const float4* __restrict__ gates,
                  const float4* __restrict__ inputs,
                  const float4* __restrict__ prev,
                  float4* __restrict__ out)
{
    const int t   = threadIdx.x;
    const int gi  = t % CH;                // channel-group within block
    const int seg = t / CH;                // s-segment within chunk

    const int g    = blockIdx.x * CH + gi; // global float4 channel-group
    const int b    = g / D4;
    const int col4 = g % D4;

    const size_t row    = (size_t)b * S * D4 + col4;
    const size_t segoff = (size_t)(seg * STEPS) * D4;
    const size_t cstep  = (size_t)L * D4;  // advance one chunk along S

    __shared__ Smem sm;

    // Seed the carry pipeline: chunk 0 (parity 0) reads shC[1].
    if (seg == SEG - 1) {
        sm.shC[1][gi] = prev[(size_t)b * D4 + col4];
    }
    // (ordered before chunk 0's reads by chunk 0's own __syncthreads)

    float4 a0[STEPS], v0[STEPS], a1[STEPS], v1[STEPS];

    // Prime the pipeline with chunk 0.
    load_chunk(gates, inputs, row + segoff, a0, v0);

#pragma unroll 1
    for (int c = 0; c < C; c += 2) {
        const size_t b0 = row + segoff + (size_t)c * cstep;
        const size_t b1 = b0 + cstep;

        // Prefetch chunk c+1 while chunk c computes.
        if (c + 1 < C) load_chunk(gates, inputs, b1, a1, v1);
        process_chunk<0>(a0, v0, b0, out, sm, seg, gi);

        // Prefetch chunk c+2 while chunk c+1 computes.
        if (c + 2 < C) load_chunk(gates, inputs, b1 + cstep, a0, v0);
        if (c + 1 < C) process_chunk<1>(a1, v1, b1, out, sm, seg, gi);
    }
}

extern "C" void kernel_launch(void* const* d_in, const int* in_sizes, int n_in,
                              void* d_out, int out_size)
{
    const float4* gates  = (const float4*)d_in[0];
    const float4* inputs = (const float4*)d_in[1];
    const float4* prev   = (const float4*)d_in[2];
    float4* out          = (float4*)d_out;

    assoc_scan_kernel<<<NB, TD>>>(gates, inputs, prev, out);
}

// round 13
// speedup vs baseline: 1.0434x; 1.0434x over previous
#include <cuda_runtime.h>
#include <cuda_bf16.h>
#include <cstdint>

// Problem shape (fixed by the dataset)
static constexpr int B  = 4;
static constexpr int S  = 4096;
static constexpr int D  = 4096;
static constexpr int D4 = D / 4;             // 1024 float4 per (b, s) row

// Tiling: each block owns CH float4-channels for the FULL sequence.
// Best empirical config (R7): TD=256, 2 CTAs/SM, streaming ld/st, one barrier/chunk.
static constexpr int CH    = 16;             // float4 channel-groups per block (64 scalar channels)
static constexpr int SEG   = 16;             // s-segments per chunk
static constexpr int STEPS = 4;              // s-steps per thread per chunk
static constexpr int L     = SEG * STEPS;    // 64 s-steps per chunk
static constexpr int C     = S / L;          // 64 chunks, processed serially per block
static constexpr int TD    = CH * SEG;       // 256 threads
static constexpr int NB    = (B * D4) / CH;  // 256 blocks (single wave @ 2 CTAs/SM)

__device__ __forceinline__ float4 f4_fma(float4 a, float4 b, float4 c) {
    return make_float4(fmaf(a.x, b.x, c.x), fmaf(a.y, b.y, c.y),
                       fmaf(a.z, b.z, c.z), fmaf(a.w, b.w, c.w));
}
__device__ __forceinline__ float4 f4_mul(float4 a, float4 b) {
    return make_float4(a.x * b.x, a.y * b.y, a.z * b.z, a.w * b.w);
}

struct Smem {
    float4 shA[2][SEG][CH];   // parity-buffered segment aggregates (gate products)
    float4 shB[2][SEG][CH];   // parity-buffered segment aggregates (scan tails)
    float4 shC[2][CH];        // parity-buffered inter-chunk carry broadcast
};

__device__ __forceinline__ void load_chunk(const float4* __restrict__ gates,
                                           const float4* __restrict__ inputs,
                                           size_t base,
                                           float4 (&a)[STEPS], float4 (&v)[STEPS])
{
#pragma unroll
    for (int i = 0; i < STEPS; i++) a[i] = __ldcs(&gates[base + (size_t)i * D4]);
#pragma unroll
    for (int i = 0; i < STEPS; i++) v[i] = __ldcs(&inputs[base + (size_t)i * D4]);
}

// Process one resident chunk. P = compile-time parity. ONE barrier per chunk.
template <int P>
__device__ __forceinline__ void process_chunk(float4 (&a)[STEPS], float4 (&v)[STEPS],
                                              size_t base,
                                              float4* __restrict__ out,
                                              Smem& sm, int seg, int gi)
{
    // Local scan within segment: a -> cumulative gate product, v -> zero-init scan.
#pragma unroll
    for (int i = 1; i < STEPS; i++) {
        v[i] = f4_fma(a[i], v[i - 1], v[i]);
        a[i] = f4_mul(a[i], a[i - 1]);
    }

    // Publish segment aggregate into this chunk's parity buffer.
    sm.shA[P][seg][gi] = a[STEPS - 1];
    sm.shB[P][seg][gi] = v[STEPS - 1];
    __syncthreads();   // orders: this write -> all reads below; prev-chunk carry write -> read

    // Carry entering this chunk (broadcast by last chunk's last-segment threads, or seeded pv).
    const float4 cv = sm.shC[P ^ 1][gi];

    // Exclusive prefix over earlier segments only (avg SEG/2 iterations).
    float4 PA = make_float4(1.f, 1.f, 1.f, 1.f);
    float4 PB = make_float4(0.f, 0.f, 0.f, 0.f);
    for (int j = 0; j < seg; j++) {
        const float4 Aj = sm.shA[P][j][gi];
        const float4 Bj = sm.shB[P][j][gi];
        PB = f4_fma(Aj, PB, Bj);
        PA = f4_mul(Aj, PA);
    }

    // State at segment start.
    const float4 ss = f4_fma(PA, cv, PB);

    // Last segment broadcasts next chunk's carry (read after NEXT chunk's barrier).
    if (seg == SEG - 1) {
        sm.shC[P][gi] = f4_fma(a[STEPS - 1], ss, v[STEPS - 1]);
    }

    // Fix up and store (streaming STG.128: prompt, orderly write bursts).
#pragma unroll
    for (int i = 0; i < STEPS; i++) {
        __stcs(&out[base + (size_t)i * D4], f4_fma(a[i], ss, v[i]));
    }
}

__global__ void __launch_bounds__(TD, 2)
assoc_scan_kernel(const float4* __restrict__ gates,
                  const float4* __restrict__ inputs,
                  const float4* __restrict__ prev,
                  float4* __restrict__ out)
{
    const int t   = threadIdx.x;
    const int gi  = t % CH;                // channel-group within block
    const int seg = t / CH;                // s-segment within chunk

    const int g    = blockIdx.x * CH + gi; // global float4 channel-group
    const int b    = g / D4;
    const int col4 = g % D4;

    const size_t row    = (size_t)b * S * D4 + col4;
    const size_t segoff = (size_t)(seg * STEPS) * D4;
    const size_t cstep  = (size_t)L * D4;  // advance one chunk along S

    __shared__ Smem sm;

    // Seed the carry pipeline: chunk 0 (parity 0) reads shC[1].
    if (seg == SEG - 1) {
        sm.shC[1][gi] = prev[(size_t)b * D4 + col4];
    }
    // (ordered before chunk 0's reads by chunk 0's own __syncthreads)

    float4 a0[STEPS], v0[STEPS], a1[STEPS], v1[STEPS];

    // Prime the pipeline with chunk 0.
    load_chunk(gates, inputs, row + segoff, a0, v0);

#pragma unroll 1
    for (int c = 0; c < C; c += 2) {
        const size_t b0 = row + segoff + (size_t)c * cstep;
        const size_t b1 = b0 + cstep;

        // Prefetch chunk c+1 while chunk c computes.
        if (c + 1 < C) load_chunk(gates, inputs, b1, a1, v1);
        process_chunk<0>(a0, v0, b0, out, sm, seg, gi);

        // Prefetch chunk c+2 while chunk c+1 computes.
        if (c + 2 < C) load_chunk(gates, inputs, b1 + cstep, a0, v0);
        if (c + 1 < C) process_chunk<1>(a1, v1, b1, out, sm, seg, gi);
    }
}

extern "C" void kernel_launch(void* const* d_in, const int* in_sizes, int n_in,
                              void* d_out, int out_size)
{
    const float4* gates  = (const float4*)d_in[0];
    const float4* inputs = (const float4*)d_in[1];
    const float4* prev   = (const float4*)d_in[2];
    float4* out          = (float4*)d_out;

    assoc_scan_kernel<<<NB, TD>>>(gates, inputs, prev, out);
}

// round 14
// speedup vs baseline: 1.0546x; 1.0107x over previous
#include <cuda_runtime.h>
#include <cuda_bf16.h>
#include <cstdint>

// Problem shape (fixed by the dataset)
static constexpr int B  = 4;
static constexpr int S  = 4096;
static constexpr int D  = 4096;
static constexpr int D4 = D / 4;             // 1024 float4 per (b, s) row

// Tiling: each block owns CH float4-channels for the FULL sequence.
// Champion config (R7/R13): TD=256, 2 CTAs/SM, streaming ld/st, one barrier/chunk.
// Measured at ~6.6TB/s = ~96% of the B300 LTS full-chip throughput cap.
static constexpr int CH    = 16;             // float4 channel-groups per block (64 scalar channels)
static constexpr int SEG   = 16;             // s-segments per chunk
static constexpr int STEPS = 4;              // s-steps per thread per chunk
static constexpr int L     = SEG * STEPS;    // 64 s-steps per chunk
static constexpr int C     = S / L;          // 64 chunks, processed serially per block
static constexpr int TD    = CH * SEG;       // 256 threads
static constexpr int NB    = (B * D4) / CH;  // 256 blocks (single wave @ 2 CTAs/SM)

__device__ __forceinline__ float4 f4_fma(float4 a, float4 b, float4 c) {
    return make_float4(fmaf(a.x, b.x, c.x), fmaf(a.y, b.y, c.y),
                       fmaf(a.z, b.z, c.z), fmaf(a.w, b.w, c.w));
}
__device__ __forceinline__ float4 f4_mul(float4 a, float4 b) {
    return make_float4(a.x * b.x, a.y * b.y, a.z * b.z, a.w * b.w);
}

struct Smem {
    float4 shA[2][SEG][CH];   // parity-buffered segment aggregates (gate products)
    float4 shB[2][SEG][CH];   // parity-buffered segment aggregates (scan tails)
    float4 shC[2][CH];        // parity-buffered inter-chunk carry broadcast
};

__device__ __forceinline__ void load_chunk(const float4* __restrict__ gates,
                                           const float4* __restrict__ inputs,
                                           size_t base,
                                           float4 (&a)[STEPS], float4 (&v)[STEPS])
{
#pragma unroll
    for (int i = 0; i < STEPS; i++) a[i] = __ldcs(&gates[base + (size_t)i * D4]);
#pragma unroll
    for (int i = 0; i < STEPS; i++) v[i] = __ldcs(&inputs[base + (size_t)i * D4]);
}

// Process one resident chunk. P = compile-time parity. ONE barrier per chunk.
template <int P>
__device__ __forceinline__ void process_chunk(float4 (&a)[STEPS], float4 (&v)[STEPS],
                                              size_t base,
                                              float4* __restrict__ out,
                                              Smem& sm, int seg, int gi)
{
    // Local scan within segment: a -> cumulative gate product, v -> zero-init scan.
#pragma unroll
    for (int i = 1; i < STEPS; i++) {
        v[i] = f4_fma(a[i], v[i - 1], v[i]);
        a[i] = f4_mul(a[i], a[i - 1]);
    }

    // Publish segment aggregate into this chunk's parity buffer.
    sm.shA[P][seg][gi] = a[STEPS - 1];
    sm.shB[P][seg][gi] = v[STEPS - 1];
    __syncthreads();   // orders: this write -> all reads below; prev-chunk carry write -> read

    // Carry entering this chunk (broadcast by last chunk's last-segment threads, or seeded pv).
    const float4 cv = sm.shC[P ^ 1][gi];

    // Exclusive prefix over earlier segments only (avg SEG/2 iterations).
    float4 PA = make_float4(1.f, 1.f, 1.f, 1.f);
    float4 PB = make_float4(0.f, 0.f, 0.f, 0.f);
    for (int j = 0; j < seg; j++) {
        const float4 Aj = sm.shA[P][j][gi];
        const float4 Bj = sm.shB[P][j][gi];
        PB = f4_fma(Aj, PB, Bj);
        PA = f4_mul(Aj, PA);
    }

    // State at segment start.
    const float4 ss = f4_fma(PA, cv, PB);

    // Last segment broadcasts next chunk's carry (read after NEXT chunk's barrier).
    if (seg == SEG - 1) {
        sm.shC[P][gi] = f4_fma(a[STEPS - 1], ss, v[STEPS - 1]);
    }

    // Fix up and store (streaming STG.128: prompt, orderly write bursts).
#pragma unroll
    for (int i = 0; i < STEPS; i++) {
        __stcs(&out[base + (size_t)i * D4], f4_fma(a[i], ss, v[i]));
    }
}

__global__ void __launch_bounds__(TD, 2)
assoc_scan_kernel(const float4* __restrict__ gates,
                  const float4* __restrict__ inputs,
                  const float4* __restrict__ prev,
                  float4* __restrict__ out)
{
    const int t   = threadIdx.x;
    const int gi  = t % CH;                // channel-group within block
    const int seg = t / CH;                // s-segment within chunk

    const int g    = blockIdx.x * CH + gi; // global float4 channel-group
    const int b    = g / D4;
    const int col4 = g % D4;

    const size_t row    = (size_t)b * S * D4 + col4;
    const size_t segoff = (size_t)(seg * STEPS) * D4;
    const size_t cstep  = (size_t)L * D4;  // advance one chunk along S

    __shared__ Smem sm;

    // Seed the carry pipeline: chunk 0 (parity 0) reads shC[1].
    if (seg == SEG - 1) {
        sm.shC[1][gi] = prev[(size_t)b * D4 + col4];
    }
    // (ordered before chunk 0's reads by chunk 0's own __syncthreads)

    float4 a0[STEPS], v0[STEPS], a1[STEPS], v1[STEPS];

    // Prime the pipeline with chunk 0.
    load_chunk(gates, inputs, row + segoff, a0, v0);

#pragma unroll 1
    for (int c = 0; c < C; c += 2) {
        const size_t b0 = row + segoff + (size_t)c * cstep;
        const size_t b1 = b0 + cstep;

        // Prefetch chunk c+1 while chunk c computes.
        if (c + 1 < C) load_chunk(gates, inputs, b1, a1, v1);
        process_chunk<0>(a0, v0, b0, out, sm, seg, gi);

        // Prefetch chunk c+2 while chunk c+1 computes.
        if (c + 2 < C) load_chunk(gates, inputs, b1 + cstep, a0, v0);
        if (c + 1 < C) process_chunk<1>(a1, v1, b1, out, sm, seg, gi);
    }
}

extern "C" void kernel_launch(void* const* d_in, const int* in_sizes, int n_in,
                              void* d_out, int out_size)
{
    const float4* gates  = (const float4*)d_in[0];
    const float4* inputs = (const float4*)d_in[1];
    const float4* prev   = (const float4*)d_in[2];
    float4* out          = (float4*)d_out;

    assoc_scan_kernel<<<NB, TD>>>(gates, inputs, prev, out);
}

// round 15
// speedup vs baseline: 1.0574x; 1.0027x over previous
#include <cuda_runtime.h>
#include <cuda_bf16.h>
#include <cstdint>

// Problem shape (fixed by the dataset)
static constexpr int B  = 4;
static constexpr int S  = 4096;
static constexpr int D  = 4096;
static constexpr int D4 = D / 4;             // 1024 float4 per (b, s) row

// Tiling: each block owns CH float4-channels for the FULL sequence.
// Champion config: TD=256, 2 CTAs/SM, streaming ld/st, one barrier/chunk.
// Measured at ~6.6TB/s = ~96% of the B300 full-chip LTS throughput cap
// (path-independent ~6300 B/cyc); traffic is the essential 768MB exactly once.
static constexpr int CH    = 16;             // float4 channel-groups per block (64 scalar channels)
static constexpr int SEG   = 16;             // s-segments per chunk
static constexpr int STEPS = 4;              // s-steps per thread per chunk
static constexpr int L     = SEG * STEPS;    // 64 s-steps per chunk
static constexpr int C     = S / L;          // 64 chunks, processed serially per block
static constexpr int TD    = CH * SEG;       // 256 threads
static constexpr int NB    = (B * D4) / CH;  // 256 blocks (single wave @ 2 CTAs/SM)

__device__ __forceinline__ float4 f4_fma(float4 a, float4 b, float4 c) {
    return make_float4(fmaf(a.x, b.x, c.x), fmaf(a.y, b.y, c.y),
                       fmaf(a.z, b.z, c.z), fmaf(a.w, b.w, c.w));
}
__device__ __forceinline__ float4 f4_mul(float4 a, float4 b) {
    return make_float4(a.x * b.x, a.y * b.y, a.z * b.z, a.w * b.w);
}

struct Smem {
    float4 shA[2][SEG][CH];   // parity-buffered segment aggregates (gate products)
    float4 shB[2][SEG][CH];   // parity-buffered segment aggregates (scan tails)
    float4 shC[2][CH];        // parity-buffered inter-chunk carry broadcast
};

__device__ __forceinline__ void load_chunk(const float4* __restrict__ gates,
                                           const float4* __restrict__ inputs,
                                           size_t base,
                                           float4 (&a)[STEPS], float4 (&v)[STEPS])
{
#pragma unroll
    for (int i = 0; i < STEPS; i++) a[i] = __ldcs(&gates[base + (size_t)i * D4]);
#pragma unroll
    for (int i = 0; i < STEPS; i++) v[i] = __ldcs(&inputs[base + (size_t)i * D4]);
}

// Process one resident chunk. P = compile-time parity. ONE barrier per chunk.
template <int P>
__device__ __forceinline__ void process_chunk(float4 (&a)[STEPS], float4 (&v)[STEPS],
                                              size_t base,
                                              float4* __restrict__ out,
                                              Smem& sm, int seg, int gi)
{
    // Local scan within segment: a -> cumulative gate product, v -> zero-init scan.
#pragma unroll
    for (int i = 1; i < STEPS; i++) {
        v[i] = f4_fma(a[i], v[i - 1], v[i]);
        a[i] = f4_mul(a[i], a[i - 1]);
    }

    // Publish segment aggregate into this chunk's parity buffer.
    sm.shA[P][seg][gi] = a[STEPS - 1];
    sm.shB[P][seg][gi] = v[STEPS - 1];
    __syncthreads();   // orders: this write -> all reads below; prev-chunk carry write -> read

    // Carry entering this chunk (broadcast by last chunk's last-segment threads, or seeded pv).
    const float4 cv = sm.shC[P ^ 1][gi];

    // Exclusive prefix over earlier segments only (avg SEG/2 iterations).
    float4 PA = make_float4(1.f, 1.f, 1.f, 1.f);
    float4 PB = make_float4(0.f, 0.f, 0.f, 0.f);
    for (int j = 0; j < seg; j++) {
        const float4 Aj = sm.shA[P][j][gi];
        const float4 Bj = sm.shB[P][j][gi];
        PB = f4_fma(Aj, PB, Bj);
        PA = f4_mul(Aj, PA);
    }

    // State at segment start.
    const float4 ss = f4_fma(PA, cv, PB);

    // Last segment broadcasts next chunk's carry (read after NEXT chunk's barrier).
    if (seg == SEG - 1) {
        sm.shC[P][gi] = f4_fma(a[STEPS - 1], ss, v[STEPS - 1]);
    }

    // Fix up and store (streaming STG.128: prompt, orderly write bursts).
#pragma unroll
    for (int i = 0; i < STEPS; i++) {
        __stcs(&out[base + (size_t)i * D4], f4_fma(a[i], ss, v[i]));
    }
}

__global__ void __launch_bounds__(TD, 2)
assoc_scan_kernel(const float4* __restrict__ gates,
                  const float4* __restrict__ inputs,
                  const float4* __restrict__ prev,
                  float4* __restrict__ out)
{
    const int t   = threadIdx.x;
    const int gi  = t % CH;                // channel-group within block
    const int seg = t / CH;                // s-segment within chunk

    const int g    = blockIdx.x * CH + gi; // global float4 channel-group
    const int b    = g / D4;
    const int col4 = g % D4;

    const size_t row    = (size_t)b * S * D4 + col4;
    const size_t segoff = (size_t)(seg * STEPS) * D4;
    const size_t cstep  = (size_t)L * D4;  // advance one chunk along S

    __shared__ Smem sm;

    // Seed the carry pipeline: chunk 0 (parity 0) reads shC[1].
    if (seg == SEG - 1) {
        sm.shC[1][gi] = prev[(size_t)b * D4 + col4];
    }
    // (ordered before chunk 0's reads by chunk 0's own __syncthreads)

    float4 a0[STEPS], v0[STEPS], a1[STEPS], v1[STEPS];

    // Prime the pipeline with chunk 0.
    load_chunk(gates, inputs, row + segoff, a0, v0);

#pragma unroll 1
    for (int c = 0; c < C; c += 2) {
        const size_t b0 = row + segoff + (size_t)c * cstep;
        const size_t b1 = b0 + cstep;

        // Prefetch chunk c+1 while chunk c computes.
        if (c + 1 < C) load_chunk(gates, inputs, b1, a1, v1);
        process_chunk<0>(a0, v0, b0, out, sm, seg, gi);

        // Prefetch chunk c+2 while chunk c+1 computes.
        if (c + 2 < C) load_chunk(gates, inputs, b1 + cstep, a0, v0);
        if (c + 1 < C) process_chunk<1>(a1, v1, b1, out, sm, seg, gi);
    }
}

extern "C" void kernel_launch(void* const* d_in, const int* in_sizes, int n_in,
                              void* d_out, int out_size)
{
    const float4* gates  = (const float4*)d_in[0];
    const float4* inputs = (const float4*)d_in[1];
    const float4* prev   = (const float4*)d_in[2];
    float4* out          = (float4*)d_out;

    assoc_scan_kernel<<<NB, TD>>>(gates, inputs, prev, out);
}